// round 16
// baseline (speedup 1.0000x reference)
#include <cuda_runtime.h>
#include <cuda_bf16.h>
#include <cstdint>

// Problem: x [16, 256, 128, 128] f32.
//  1) weight[b,c] = mean over H,W
//  2) idx[b,:] = argsort(weight[b]) ascending, take first 16 (stable)
//  3) out[b,k,:,:] = x[b, idx[b,k], :, :]
//
// R16 = R10 (best measured structure: 4096 pristine mean blocks first,
// 2048 eighth-plane gather blocks strictly after, last-finisher select,
// self-resetting sync, ONE graph node) with ONE change:
//   gather stores are DEFAULT WRITE-BACK (not __stcs) and gather reads are
//   __ldcg (L2-only). The 16 MiB output fits in the 126 MB L2 as dirty
//   lines, so its DRAM write traffic leaves the measured critical path;
//   evicted input lines are clean (no writeback cost).

#define B 16
#define C 256
#define HW 16384          // 128*128
#define K 16
#define MEAN_BLOCKS 4096
#define GATHER_BLOCKS 2048   // 8 per output plane (eighth planes)

__device__ float    g_weight[B * C];
__device__ int      g_idx[B * K];
__device__ int      g_mdone[B];       // mean completions (reset by select)
__device__ unsigned g_ready_mask;     // bit b = select published
__device__ int      g_exit;           // exit ticket (self-reset)

__global__ __launch_bounds__(256, 8) void fused_kernel(const float* __restrict__ x,
                                                       float* __restrict__ out) {
    const int bid = blockIdx.x;
    const int t   = threadIdx.x;

    if (bid < MEAN_BLOCKS) {
        // ================= Phase A: mean of plane bid (pristine) =============
        const int b = bid >> 8;
        const float4* __restrict__ p =
            reinterpret_cast<const float4*>(x + (size_t)bid * HW);
        float s0 = 0.f, s1 = 0.f, s2 = 0.f, s3 = 0.f;
#pragma unroll
        for (int i = 0; i < 16; i += 4) {
            float4 v0 = __ldg(&p[t + (i + 0) * 256]);
            float4 v1 = __ldg(&p[t + (i + 1) * 256]);
            float4 v2 = __ldg(&p[t + (i + 2) * 256]);
            float4 v3 = __ldg(&p[t + (i + 3) * 256]);
            s0 += (v0.x + v0.y) + (v0.z + v0.w);
            s1 += (v1.x + v1.y) + (v1.z + v1.w);
            s2 += (v2.x + v2.y) + (v2.z + v2.w);
            s3 += (v3.x + v3.y) + (v3.z + v3.w);
        }
        float s = (s0 + s1) + (s2 + s3);
#pragma unroll
        for (int off = 16; off > 0; off >>= 1)
            s += __shfl_down_sync(0xFFFFFFFFu, s, off);

        __shared__ float sred[8];
        __shared__ int   s_last;
        if ((t & 31) == 0) sred[t >> 5] = s;
        __syncthreads();
        if (t < 8) {
            float v = sred[t];
#pragma unroll
            for (int off = 4; off > 0; off >>= 1)
                v += __shfl_down_sync(0xFFu, v, off);
            if (t == 0) {
                g_weight[bid] = v * (1.0f / (float)HW);
                __threadfence();                       // publish mean
                const int old = atomicAdd(&g_mdone[b], 1);
                s_last = (old == C - 1);               // last finisher
            }
        }
        __syncthreads();
        if (!s_last) return;

        // ---- last mean block of batch b: stable bottom-16 select ----
        __threadfence();
        __shared__ float sw[C];
        sw[t] = __ldcg(&g_weight[b * C + t]);
        __syncthreads();

        const float v = sw[t];
        int rank = 0;
#pragma unroll 8
        for (int j = 0; j < C; ++j) {
            const float u = sw[j];
            rank += (u < v) || (u == v && j < t);
        }
        if (rank < K) g_idx[b * K + rank] = t;
        __syncthreads();
        if (t == 0) {
            atomicExch(&g_mdone[b], 0);                // self-reset for replay
            __threadfence();                           // publish g_idx
            atomicOr(&g_ready_mask, 1u << b);          // announce ready
        }
        return;
    }

    // ============ Phase B: gather, 2048 eighth-plane blocks ============
    const int g     = bid - MEAN_BLOCKS;               // 0..2047
    const int plane = g >> 3;                          // 0..255
    const int q     = g & 7;                           // eighth of plane
    const int b     = plane >> 4;

    if (t == 0) {
        while (((atomicAdd(&g_ready_mask, 0u) >> b) & 1u) == 0) __nanosleep(64);
    }
    __syncthreads();                                   // acquire for block

    const int c = __ldcg(&g_idx[plane]);

    const float4* __restrict__ src = reinterpret_cast<const float4*>(
        x + ((size_t)b * C + c) * HW) + q * 512;
    float4* __restrict__ dst = reinterpret_cast<float4*>(
        out + (size_t)plane * HW) + q * 512;

    // L2-only reads; DEFAULT write-back stores (output stays dirty in L2,
    // its DRAM write leaves the measured critical path)
    float4 w0 = __ldcg(&src[t]);
    float4 w1 = __ldcg(&src[t + 256]);
    dst[t]       = w0;
    dst[t + 256] = w1;

    // exit ticket: last gather block resets the ready mask
    __syncthreads();
    if (t == 0) {
        const int old = atomicAdd(&g_exit, 1);
        if (old == GATHER_BLOCKS - 1) {
            g_ready_mask = 0u;
            __threadfence();
            atomicExch(&g_exit, 0);                    // replay-safe
        }
    }
}

// ---------------------------------------------------------------------------
extern "C" void kernel_launch(void* const* d_in, const int* in_sizes, int n_in,
                              void* d_out, int out_size) {
    const float* x = (const float*)d_in[0];
    float* out = (float*)d_out;

    fused_kernel<<<MEAN_BLOCKS + GATHER_BLOCKS, 256>>>(x, out);
}